// round 4
// baseline (speedup 1.0000x reference)
#include <cuda_runtime.h>

#define R 16
#define A 8
#define THREADS 256

// Precomputed, row-invariant parameters (written by precompute_kernel once per launch).
__device__ float g_m[R * A];    // centers
__device__ float g_gb[R * A];   // -0.5*log2(e) / max(s1,s2)^2   -> UU (mu_big) coefficient
__device__ float g_gs[R * A];   // -0.5*log2(e) / min(s1,s2)^2   -> LL (mu_small) coefficient
__device__ float g_c1n[R], g_c2n[R];   // c1, c2 in natural (rule) order
__device__ float g_c1s[R], g_c2s[R];   // c1, c2 sorted ascending
__device__ int   g_p1[R],  g_p2[R];    // perm: sorted position j -> rule index

__global__ void precompute_kernel(const float* __restrict__ W,
                                  const float* __restrict__ c1,
                                  const float* __restrict__ c2) {
    int t = threadIdx.x;
    if (t < R * A) {
        // offsets = A*r + a == t ; m = W[t], s1 = W[t+1], s2 = W[t+2]
        float m  = W[t];
        float s1 = W[t + 1];
        float s2 = W[t + 2];
        float smax = fmaxf(s1, s2);
        float smin = fminf(s1, s2);
        const float k = -0.5f * 1.44269504088896340736f;  // -0.5 * log2(e)
        g_m[t]  = m;
        g_gb[t] = k / (smax * smax);   // larger sigma -> bigger membership -> mu_big
        g_gs[t] = k / (smin * smin);   // smaller sigma -> smaller membership -> mu_small
    }
    if (t < R) {
        g_c1n[t] = c1[t];
        g_c2n[t] = c2[t];
    }
    if (t == 0) {
        int p[R]; float v[R];
        for (int i = 0; i < R; i++) { p[i] = i; v[i] = c1[i]; }
        for (int i = 1; i < R; i++) {
            float key = v[i]; int kp = p[i]; int j = i - 1;
            while (j >= 0 && v[j] > key) { v[j + 1] = v[j]; p[j + 1] = p[j]; j--; }
            v[j + 1] = key; p[j + 1] = kp;
        }
        for (int i = 0; i < R; i++) { g_p1[i] = p[i]; g_c1s[i] = v[i]; }
    }
    if (t == 1) {
        int p[R]; float v[R];
        for (int i = 0; i < R; i++) { p[i] = i; v[i] = c2[i]; }
        for (int i = 1; i < R; i++) {
            float key = v[i]; int kp = p[i]; int j = i - 1;
            while (j >= 0 && v[j] > key) { v[j + 1] = v[j]; p[j + 1] = p[j]; j--; }
            v[j + 1] = key; p[j + 1] = kp;
        }
        for (int i = 0; i < R; i++) { g_p2[i] = p[i]; g_c2s[i] = v[i]; }
    }
}

__device__ __forceinline__ float ex2f(float x) {
    float r;
    asm("ex2.approx.f32 %0, %1;" : "=f"(r) : "f"(x));
    return r;
}

__global__ __launch_bounds__(THREADS)
void t2fls_kernel(const float* __restrict__ x_in,
                  float* __restrict__ out, int n) {
    __shared__ float sm_m[R * A], sm_gb[R * A], sm_gs[R * A];
    __shared__ float sc1[R], sc2[R], sc1s[R], sc2s[R];
    __shared__ int   sp1[R], sp2[R];
    __shared__ float shU[R][THREADS];
    __shared__ float shL[R][THREADS];

    int t = threadIdx.x;
    if (t < R * A) { sm_m[t] = g_m[t]; sm_gb[t] = g_gb[t]; sm_gs[t] = g_gs[t]; }
    if (t < R) {
        sc1[t] = g_c1n[t]; sc2[t] = g_c2n[t];
        sc1s[t] = g_c1s[t]; sc2s[t] = g_c2s[t];
        sp1[t] = g_p1[t];  sp2[t] = g_p2[t];
    }
    __syncthreads();

    int i = blockIdx.x * THREADS + t;
    if (i >= n) return;

    // Load the 8-feature row with two float4s.
    const float4* xp = (const float4*)(x_in + (size_t)i * A);
    float4 a0 = xp[0];
    float4 a1 = xp[1];
    float x[A] = {a0.x, a0.y, a0.z, a0.w, a1.x, a1.y, a1.z, a1.w};

    float s0 = 0.f, t0 = 0.f;     // sum(c1*L), sum(L)
    float s0r = 0.f, t0r = 0.f;   // sum(c2*U), sum(U)

    #pragma unroll
    for (int r = 0; r < R; r++) {
        float su = 0.f, sl = 0.f;
        #pragma unroll
        for (int a = 0; a < A; a++) {
            float d = x[a] - sm_m[r * A + a];
            float e = d * d;
            su = fmaf(e, sm_gb[r * A + a], su);
            sl = fmaf(e, sm_gs[r * A + a], sl);
        }
        float U = ex2f(su);   // prod_a mu_big  = exp2(sum of scaled exponents)
        float L = ex2f(sl);   // prod_a mu_small
        shU[r][t] = U;
        shL[r][t] = L;
        s0  = fmaf(sc1[r], L, s0);   t0  += L;
        s0r = fmaf(sc2[r], U, s0r);  t0r += U;
    }

    float left  = __fdividef(s0,  t0);
    float right = __fdividef(s0r, t0r);

    float cs = 0.f, ct = 0.f, csr = 0.f, ctr = 0.f;
    #pragma unroll
    for (int j = 0; j < R; j++) {
        int r1 = sp1[j];
        float d = shU[r1][t] - shL[r1][t];
        cs = fmaf(sc1s[j], d, cs);
        ct += d;
        left = fminf(left, __fdividef(s0 + cs, t0 + ct));

        int r2 = sp2[j];
        float dr = shL[r2][t] - shU[r2][t];
        csr = fmaf(sc2s[j], dr, csr);
        ctr += dr;
        right = fmaxf(right, __fdividef(s0r + csr, t0r + ctr));
    }

    out[i] = 0.5f * (left + right);
}

extern "C" void kernel_launch(void* const* d_in, const int* in_sizes, int n_in,
                              void* d_out, int out_size) {
    const float* x  = (const float*)d_in[0];
    const float* W  = (const float*)d_in[1];
    const float* c1 = (const float*)d_in[2];
    const float* c2 = (const float*)d_in[3];
    float* out = (float*)d_out;
    int n = out_size;  // one output per row

    precompute_kernel<<<1, 128>>>(W, c1, c2);
    int blocks = (n + THREADS - 1) / THREADS;
    t2fls_kernel<<<blocks, THREADS>>>(x, out, n);
}

// round 5
// speedup vs baseline: 1.1969x; 1.1969x over previous
#include <cuda_runtime.h>

#define R 16
#define A 8
#define THREADS 256

typedef unsigned long long ull;

// Packed f32x2 ops (Blackwell): operate on register pairs holding (lo, hi) floats.
#define ADD2(o, a, b)     asm("add.rn.f32x2 %0, %1, %2;"     : "=l"(o) : "l"(a), "l"(b))
#define MUL2(o, a, b)     asm("mul.rn.f32x2 %0, %1, %2;"     : "=l"(o) : "l"(a), "l"(b))
#define FMA2(o, a, b, c)  asm("fma.rn.f32x2 %0, %1, %2, %3;" : "=l"(o) : "l"(a), "l"(b), "l"(c))
#define PACK2(o, lo, hi)  asm("mov.b64 %0, {%1, %2};"        : "=l"(o) : "f"(lo), "f"(hi))
#define UNPACK2(lo, hi, i) asm("mov.b64 {%0, %1}, %2;"       : "=f"(lo), "=f"(hi) : "l"(i))

__device__ __forceinline__ float ex2f(float x) {
    float r;
    asm("ex2.approx.f32 %0, %1;" : "=f"(r) : "f"(x));
    return r;
}

__global__ __launch_bounds__(THREADS)
void t2fls_kernel(const float* __restrict__ x_in,
                  const float* __restrict__ W,
                  const float* __restrict__ c1,
                  const float* __restrict__ c2,
                  float* __restrict__ out, int n)
{
    // Per-thread private d = U-L, runtime-indexable for the c2-order scan.
    // Column t is touched only by thread t (no cross-thread sharing, no sync needed).
    __shared__ float shD[R][THREADS];
    // Coefficients in c1-sorted rule order, packed as pairs (v[a], v[a+4]):
    // u64 k of rule j holds floats ( v[j][k&3], v[j][(k&3)+4] ) ... laid out for ulonglong2 loads.
    __shared__ __align__(16) ull sh_nm[R][4];   // negated centers
    __shared__ __align__(16) ull sh_gb[R][4];   // -0.5*log2(e)/smax^2  (mu_big / U)
    __shared__ __align__(16) ull sh_gs[R][4];   // -0.5*log2(e)/smin^2  (mu_small / L)
    // Per sorted slot j: (c1s[j], c2s[j], as_float(q[j]*THREADS), c2[p1[j]])
    __shared__ float4 shScan[R];
    __shared__ int   sh_p1[R], sh_inv1[R], sh_p2[R];
    __shared__ float sh_c1s[R], sh_c2s[R];

    int t = threadIdx.x;

    // ---- Phase A: parallel rank-sort of c1 (threads 0..15) and c2 (threads 16..31) ----
    if (t < R) {
        float cj = c1[t];
        int rank = 0;
        #pragma unroll
        for (int i = 0; i < R; i++) {
            float ci = c1[i];
            rank += (ci < cj) || (ci == cj && i < t);   // stable
        }
        sh_p1[rank] = t;
        sh_inv1[t] = rank;
        sh_c1s[rank] = cj;
    } else if (t < 2 * R) {
        int j = t - R;
        float cj = c2[j];
        int rank = 0;
        #pragma unroll
        for (int i = 0; i < R; i++) {
            float ci = c2[i];
            rank += (ci < cj) || (ci == cj && i < j);   // stable
        }
        sh_p2[rank] = j;
        sh_c2s[rank] = cj;
    }
    __syncthreads();

    // ---- Phase B: coefficient transform into c1-sorted, pair-packed layout ----
    if (t < R * A) {
        int r = t >> 3, a = t & 7;
        // offsets = A*r + a == t ; m = W[t], s1 = W[t+1], s2 = W[t+2]
        float m  = W[t];
        float s1 = W[t + 1];
        float s2 = W[t + 2];
        float smax = fmaxf(s1, s2);
        float smin = fminf(s1, s2);
        const float k = -0.5f * 1.44269504088896340736f;  // -0.5 * log2(e)
        int slot = sh_inv1[r];
        int idx = slot * 8 + (a & 3) * 2 + (a >> 2);      // pair p=(a&3), half=(a>>2)
        ((float*)sh_nm)[idx] = -m;
        ((float*)sh_gb)[idx] = k / (smax * smax);
        ((float*)sh_gs)[idx] = k / (smin * smin);
    }
    if (t < R) {
        int q = sh_inv1[sh_p2[t]];   // slot (in c1-order storage) of rule p2[t]
        shScan[t] = make_float4(sh_c1s[t], sh_c2s[t],
                                __int_as_float(q * THREADS),
                                c2[sh_p1[t]]);           // c2 value of rule at c1-slot t
    }
    __syncthreads();

    int i = blockIdx.x * THREADS + t;
    if (i >= n) return;

    // Load the 8-feature row; pack as pairs (x[p], x[p+4]).
    const float4* xp = (const float4*)(x_in + (size_t)i * A);
    float4 a0 = xp[0];
    float4 a1 = xp[1];
    ull x2[4];
    PACK2(x2[0], a0.x, a1.x);
    PACK2(x2[1], a0.y, a1.y);
    PACK2(x2[2], a0.z, a1.z);
    PACK2(x2[3], a0.w, a1.w);

    float s0 = 0.f, t0 = 0.f;     // sum(c1*L), sum(L)
    float s0r = 0.f, t0r = 0.f;   // sum(c2*U), sum(U)
    float dreg[R];                // d = U-L in c1-sorted order (compile-time indexed)

    #pragma unroll
    for (int j = 0; j < R; j++) {
        ulonglong2 nm01 = *(const ulonglong2*)&sh_nm[j][0];
        ulonglong2 nm23 = *(const ulonglong2*)&sh_nm[j][2];
        ulonglong2 gb01 = *(const ulonglong2*)&sh_gb[j][0];
        ulonglong2 gb23 = *(const ulonglong2*)&sh_gb[j][2];
        ulonglong2 gs01 = *(const ulonglong2*)&sh_gs[j][0];
        ulonglong2 gs23 = *(const ulonglong2*)&sh_gs[j][2];
        ull nm[4] = {nm01.x, nm01.y, nm23.x, nm23.y};
        ull gb[4] = {gb01.x, gb01.y, gb23.x, gb23.y};
        ull gs[4] = {gs01.x, gs01.y, gs23.x, gs23.y};

        ull acc_b = 0ull, acc_s = 0ull;
        #pragma unroll
        for (int p = 0; p < 4; p++) {
            ull d2, e2;
            ADD2(d2, x2[p], nm[p]);        // d = x - m
            MUL2(e2, d2, d2);              // e = d*d (shared by both accs)
            FMA2(acc_b, e2, gb[p], acc_b); // su += e * gb
            FMA2(acc_s, e2, gs[p], acc_s); // sl += e * gs
        }
        float bl, bh, ql, qh;
        UNPACK2(bl, bh, acc_b);
        UNPACK2(ql, qh, acc_s);
        float U = ex2f(bl + bh);   // prod_a mu_big
        float L = ex2f(ql + qh);   // prod_a mu_small

        float4 sc = shScan[j];
        s0  = fmaf(sc.x, L, s0);   t0  += L;    // sc.x = c1 of this (sorted) rule
        s0r = fmaf(sc.w, U, s0r);  t0r += U;    // sc.w = c2 of this rule
        float dj = U - L;
        dreg[j] = dj;
        shD[j][t] = dj;
    }

    float left  = __fdividef(s0,  t0);
    float right = __fdividef(s0r, t0r);

    float cs = 0.f, ct = 0.f, csr = 0.f, ctr = 0.f;
    const float* shDf = &shD[0][0];
    #pragma unroll
    for (int j = 0; j < R; j++) {
        float4 sc = shScan[j];
        // Left scan: already in c1-sorted order -> registers.
        float dj = dreg[j];
        cs = fmaf(sc.x, dj, cs);
        ct += dj;
        left = fminf(left, __fdividef(s0 + cs, t0 + ct));
        // Right scan: c2-sorted order via runtime slot offset (same-thread shared column).
        int off = __float_as_int(sc.z);
        float dq = shDf[off + t];           // = U - L of rule p2[j]
        csr = fmaf(sc.y, dq, csr);          // accumulates  sum c2s*(U-L)
        ctr += dq;
        // dr = L - U = -dq  =>  ratio = (s0r - csr)/(t0r - ctr)
        right = fmaxf(right, __fdividef(s0r - csr, t0r - ctr));
    }

    out[i] = 0.5f * (left + right);
}

extern "C" void kernel_launch(void* const* d_in, const int* in_sizes, int n_in,
                              void* d_out, int out_size) {
    const float* x  = (const float*)d_in[0];
    const float* W  = (const float*)d_in[1];
    const float* c1 = (const float*)d_in[2];
    const float* c2 = (const float*)d_in[3];
    float* out = (float*)d_out;
    int n = out_size;  // one output per row

    int blocks = (n + THREADS - 1) / THREADS;
    t2fls_kernel<<<blocks, THREADS>>>(x, W, c1, c2, out, n);
}

// round 6
// speedup vs baseline: 1.1988x; 1.0015x over previous
#include <cuda_runtime.h>

#define R 16
#define A 8
#define THREADS 128

typedef unsigned long long ull;

// Packed f32x2 ops (Blackwell): operate on register pairs holding (lo, hi) floats.
#define ADD2(o, a, b)     asm("add.rn.f32x2 %0, %1, %2;"     : "=l"(o) : "l"(a), "l"(b))
#define MUL2(o, a, b)     asm("mul.rn.f32x2 %0, %1, %2;"     : "=l"(o) : "l"(a), "l"(b))
#define FMA2(o, a, b, c)  asm("fma.rn.f32x2 %0, %1, %2, %3;" : "=l"(o) : "l"(a), "l"(b), "l"(c))
#define PACK2(o, lo, hi)  asm("mov.b64 %0, {%1, %2};"        : "=l"(o) : "f"(lo), "f"(hi))
#define UNPACK2(lo, hi, i) asm("mov.b64 {%0, %1}, %2;"       : "=f"(lo), "=f"(hi) : "l"(i))

__device__ __forceinline__ float ex2f(float x) {
    float r;
    asm("ex2.approx.f32 %0, %1;" : "=f"(r) : "f"(x));
    return r;
}

__global__ __launch_bounds__(THREADS, 8)   // cap regs at 64 -> up to 8 CTAs/SM
void t2fls_kernel(const float* __restrict__ x_in,
                  const float* __restrict__ W,
                  const float* __restrict__ c1,
                  const float* __restrict__ c2,
                  float* __restrict__ out, int n)
{
    // Per-thread private d = U-L. Column t is touched only by thread t
    // (no cross-thread sharing, no sync needed after the prologue barrier).
    __shared__ float shD[R][THREADS];
    // Coefficients in c1-sorted rule order, packed as pairs (v[a], v[a+4]):
    // u64 k of rule j holds floats ( v[j][k&3], v[j][(k&3)+4] ), laid out for ulonglong2 loads.
    __shared__ __align__(16) ull sh_nm[R][4];   // negated centers
    __shared__ __align__(16) ull sh_gb[R][4];   // -0.5*log2(e)/smax^2  (mu_big / U)
    __shared__ __align__(16) ull sh_gs[R][4];   // -0.5*log2(e)/smin^2  (mu_small / L)
    // Per sorted slot j: (c1s[j], c2s[j], as_float(q[j]*THREADS), c2[p1[j]])
    __shared__ float4 shScan[R];
    __shared__ int   sh_p1[R], sh_inv1[R], sh_p2[R];
    __shared__ float sh_c1s[R], sh_c2s[R];

    int t = threadIdx.x;

    // ---- Phase A: parallel rank-sort of c1 (threads 0..15) and c2 (threads 16..31) ----
    if (t < R) {
        float cj = c1[t];
        int rank = 0;
        #pragma unroll
        for (int i = 0; i < R; i++) {
            float ci = c1[i];
            rank += (ci < cj) || (ci == cj && i < t);   // stable
        }
        sh_p1[rank] = t;
        sh_inv1[t] = rank;
        sh_c1s[rank] = cj;
    } else if (t < 2 * R) {
        int j = t - R;
        float cj = c2[j];
        int rank = 0;
        #pragma unroll
        for (int i = 0; i < R; i++) {
            float ci = c2[i];
            rank += (ci < cj) || (ci == cj && i < j);   // stable
        }
        sh_p2[rank] = j;
        sh_c2s[rank] = cj;
    }
    __syncthreads();

    // ---- Phase B: coefficient transform into c1-sorted, pair-packed layout ----
    {
        // THREADS == R*A == 128: every thread handles one (rule, feature).
        int r = t >> 3, a = t & 7;
        // offsets = A*r + a == t ; m = W[t], s1 = W[t+1], s2 = W[t+2]
        float m  = W[t];
        float s1 = W[t + 1];
        float s2 = W[t + 2];
        float smax = fmaxf(s1, s2);
        float smin = fminf(s1, s2);
        const float k = -0.5f * 1.44269504088896340736f;  // -0.5 * log2(e)
        int slot = sh_inv1[r];
        int idx = slot * 8 + (a & 3) * 2 + (a >> 2);      // pair p=(a&3), half=(a>>2)
        ((float*)sh_nm)[idx] = -m;
        ((float*)sh_gb)[idx] = k / (smax * smax);
        ((float*)sh_gs)[idx] = k / (smin * smin);
    }
    if (t < R) {
        int q = sh_inv1[sh_p2[t]];   // slot (in c1-order storage) of rule p2[t]
        shScan[t] = make_float4(sh_c1s[t], sh_c2s[t],
                                __int_as_float(q * THREADS),
                                c2[sh_p1[t]]);           // c2 value of rule at c1-slot t
    }
    __syncthreads();

    int i = blockIdx.x * THREADS + t;
    if (i >= n) return;

    // Load the 8-feature row; pack as pairs (x[p], x[p+4]).
    const float4* xp = (const float4*)(x_in + (size_t)i * A);
    float4 a0 = xp[0];
    float4 a1 = xp[1];
    ull x2[4];
    PACK2(x2[0], a0.x, a1.x);
    PACK2(x2[1], a0.y, a1.y);
    PACK2(x2[2], a0.z, a1.z);
    PACK2(x2[3], a0.w, a1.w);

    float s0 = 0.f, t0 = 0.f;     // sum(c1*L), sum(L)
    float s0r = 0.f, t0r = 0.f;   // sum(c2*U), sum(U)

    #pragma unroll
    for (int j = 0; j < R; j++) {
        ulonglong2 nm01 = *(const ulonglong2*)&sh_nm[j][0];
        ulonglong2 nm23 = *(const ulonglong2*)&sh_nm[j][2];
        ulonglong2 gb01 = *(const ulonglong2*)&sh_gb[j][0];
        ulonglong2 gb23 = *(const ulonglong2*)&sh_gb[j][2];
        ulonglong2 gs01 = *(const ulonglong2*)&sh_gs[j][0];
        ulonglong2 gs23 = *(const ulonglong2*)&sh_gs[j][2];

        ull acc_b = 0ull, acc_s = 0ull;
        ull d2, e2;
        ADD2(d2, x2[0], nm01.x); MUL2(e2, d2, d2);
        FMA2(acc_b, e2, gb01.x, acc_b); FMA2(acc_s, e2, gs01.x, acc_s);
        ADD2(d2, x2[1], nm01.y); MUL2(e2, d2, d2);
        FMA2(acc_b, e2, gb01.y, acc_b); FMA2(acc_s, e2, gs01.y, acc_s);
        ADD2(d2, x2[2], nm23.x); MUL2(e2, d2, d2);
        FMA2(acc_b, e2, gb23.x, acc_b); FMA2(acc_s, e2, gs23.x, acc_s);
        ADD2(d2, x2[3], nm23.y); MUL2(e2, d2, d2);
        FMA2(acc_b, e2, gb23.y, acc_b); FMA2(acc_s, e2, gs23.y, acc_s);

        float bl, bh, ql, qh;
        UNPACK2(bl, bh, acc_b);
        UNPACK2(ql, qh, acc_s);
        float U = ex2f(bl + bh);   // prod_a mu_big
        float L = ex2f(ql + qh);   // prod_a mu_small

        float4 sc = shScan[j];
        s0  = fmaf(sc.x, L, s0);   t0  += L;    // sc.x = c1 of this (sorted) rule
        s0r = fmaf(sc.w, U, s0r);  t0r += U;    // sc.w = c2 of this rule
        shD[j][t] = U - L;
    }

    float left  = __fdividef(s0,  t0);
    float right = __fdividef(s0r, t0r);

    float cs = 0.f, ct = 0.f, csr = 0.f, ctr = 0.f;
    const float* shDf = &shD[0][0];
    #pragma unroll
    for (int j = 0; j < R; j++) {
        float4 sc = shScan[j];
        // Left scan: storage is already c1-sorted -> compile-time offset.
        float dj = shD[j][t];
        cs = fmaf(sc.x, dj, cs);
        ct += dj;
        left = fminf(left, __fdividef(s0 + cs, t0 + ct));
        // Right scan: c2-sorted order via runtime slot offset (same-thread shared column).
        int off = __float_as_int(sc.z);
        float dq = shDf[off + t];           // = U - L of rule p2[j]
        csr = fmaf(sc.y, dq, csr);          // accumulates  sum c2s*(U-L)
        ctr += dq;
        // dr = L - U = -dq  =>  ratio = (s0r - csr)/(t0r - ctr)
        right = fmaxf(right, __fdividef(s0r - csr, t0r - ctr));
    }

    out[i] = 0.5f * (left + right);
}

extern "C" void kernel_launch(void* const* d_in, const int* in_sizes, int n_in,
                              void* d_out, int out_size) {
    const float* x  = (const float*)d_in[0];
    const float* W  = (const float*)d_in[1];
    const float* c1 = (const float*)d_in[2];
    const float* c2 = (const float*)d_in[3];
    float* out = (float*)d_out;
    int n = out_size;  // one output per row

    int blocks = (n + THREADS - 1) / THREADS;
    t2fls_kernel<<<blocks, THREADS>>>(x, W, c1, c2, out, n);
}

// round 7
// speedup vs baseline: 1.2212x; 1.0187x over previous
#include <cuda_runtime.h>

#define R 16
#define A 8
#define THREADS 128
#define ROWS_PER_CTA (2 * THREADS)

typedef unsigned long long ull;

// Packed f32x2 ops (Blackwell): operate on register pairs holding (lo, hi) floats.
#define ADD2(o, a, b)     asm("add.rn.f32x2 %0, %1, %2;"     : "=l"(o) : "l"(a), "l"(b))
#define MUL2(o, a, b)     asm("mul.rn.f32x2 %0, %1, %2;"     : "=l"(o) : "l"(a), "l"(b))
#define FMA2(o, a, b, c)  asm("fma.rn.f32x2 %0, %1, %2, %3;" : "=l"(o) : "l"(a), "l"(b), "l"(c))
#define PACK2(o, lo, hi)  asm("mov.b64 %0, {%1, %2};"        : "=l"(o) : "f"(lo), "f"(hi))
#define UNPACK2(lo, hi, i) asm("mov.b64 {%0, %1}, %2;"       : "=f"(lo), "=f"(hi) : "l"(i))

__device__ __forceinline__ float ex2f(float x) {
    float r;
    asm("ex2.approx.f32 %0, %1;" : "=f"(r) : "f"(x));
    return r;
}

__global__ __launch_bounds__(THREADS, 7)   // 72-reg cap -> 7 CTAs/SM, grid 1024 = single wave
void t2fls_kernel(const float* __restrict__ x_in,
                  const float* __restrict__ W,
                  const float* __restrict__ c1,
                  const float* __restrict__ c2,
                  float* __restrict__ out, int n)
{
    // d = U-L per (rule, row). Column c is touched only by the owning thread.
    __shared__ float shD[R][ROWS_PER_CTA];
    // Coefficients in c1-sorted rule order, packed as pairs (v[a], v[a+4]):
    __shared__ __align__(16) ull sh_nm[R][4];   // negated centers
    __shared__ __align__(16) ull sh_gb[R][4];   // -0.5*log2(e)/smax^2  (mu_big / U)
    __shared__ __align__(16) ull sh_gs[R][4];   // -0.5*log2(e)/smin^2  (mu_small / L)
    // Per sorted slot j: (c1s[j], c2s[j], as_float(q[j]*ROWS_PER_CTA), c2[p1[j]])
    __shared__ float4 shScan[R];
    __shared__ int   sh_p1[R], sh_inv1[R], sh_p2[R];
    __shared__ float sh_c1s[R], sh_c2s[R];

    int t = threadIdx.x;

    // ---- Phase A: parallel rank-sort of c1 (threads 0..15) and c2 (threads 16..31) ----
    if (t < R) {
        float cj = c1[t];
        int rank = 0;
        #pragma unroll
        for (int i = 0; i < R; i++) {
            float ci = c1[i];
            rank += (ci < cj) || (ci == cj && i < t);   // stable
        }
        sh_p1[rank] = t;
        sh_inv1[t] = rank;
        sh_c1s[rank] = cj;
    } else if (t < 2 * R) {
        int j = t - R;
        float cj = c2[j];
        int rank = 0;
        #pragma unroll
        for (int i = 0; i < R; i++) {
            float ci = c2[i];
            rank += (ci < cj) || (ci == cj && i < j);   // stable
        }
        sh_p2[rank] = j;
        sh_c2s[rank] = cj;
    }
    __syncthreads();

    // ---- Phase B: coefficient transform into c1-sorted, pair-packed layout ----
    {
        // THREADS == R*A == 128: every thread handles one (rule, feature).
        int r = t >> 3, a = t & 7;
        float m  = W[t];
        float s1 = W[t + 1];
        float s2 = W[t + 2];
        float smax = fmaxf(s1, s2);
        float smin = fminf(s1, s2);
        const float k = -0.5f * 1.44269504088896340736f;  // -0.5 * log2(e)
        int slot = sh_inv1[r];
        int idx = slot * 8 + (a & 3) * 2 + (a >> 2);      // pair p=(a&3), half=(a>>2)
        ((float*)sh_nm)[idx] = -m;
        ((float*)sh_gb)[idx] = k / (smax * smax);
        ((float*)sh_gs)[idx] = k / (smin * smin);
    }
    if (t < R) {
        int q = sh_inv1[sh_p2[t]];   // slot (in c1-order storage) of rule p2[t]
        shScan[t] = make_float4(sh_c1s[t], sh_c2s[t],
                                __int_as_float(q * ROWS_PER_CTA),
                                c2[sh_p1[t]]);           // c2 value of rule at c1-slot t
    }
    __syncthreads();

    int base = blockIdx.x * ROWS_PER_CTA;
    int ia = base + t;
    int ib = base + t + THREADS;
    // Clamp load indices (stores are guarded); keeps the hot path branch-free.
    int la = ia < n ? ia : (n - 1);
    int lb = ib < n ? ib : (n - 1);

    // Load the two 8-feature rows; pack as pairs (x[p], x[p+4]).
    const float4* xa = (const float4*)(x_in + (size_t)la * A);
    const float4* xb = (const float4*)(x_in + (size_t)lb * A);
    float4 a0 = xa[0], a1 = xa[1];
    float4 b0 = xb[0], b1 = xb[1];
    ull xpa[4], xpb[4];
    PACK2(xpa[0], a0.x, a1.x); PACK2(xpa[1], a0.y, a1.y);
    PACK2(xpa[2], a0.z, a1.z); PACK2(xpa[3], a0.w, a1.w);
    PACK2(xpb[0], b0.x, b1.x); PACK2(xpb[1], b0.y, b1.y);
    PACK2(xpb[2], b0.z, b1.z); PACK2(xpb[3], b0.w, b1.w);

    float s0a = 0.f, t0a = 0.f, s0ra = 0.f, t0ra = 0.f;
    float s0b = 0.f, t0b = 0.f, s0rb = 0.f, t0rb = 0.f;

    #pragma unroll
    for (int j = 0; j < R; j++) {
        ull aba = 0ull, asa = 0ull, abb = 0ull, asb = 0ull;
        ull d2, e2;
        {   // pairs 0,1
            ulonglong2 nm = *(const ulonglong2*)&sh_nm[j][0];
            ulonglong2 gb = *(const ulonglong2*)&sh_gb[j][0];
            ulonglong2 gs = *(const ulonglong2*)&sh_gs[j][0];
            ADD2(d2, xpa[0], nm.x); MUL2(e2, d2, d2);
            FMA2(aba, e2, gb.x, aba); FMA2(asa, e2, gs.x, asa);
            ADD2(d2, xpb[0], nm.x); MUL2(e2, d2, d2);
            FMA2(abb, e2, gb.x, abb); FMA2(asb, e2, gs.x, asb);
            ADD2(d2, xpa[1], nm.y); MUL2(e2, d2, d2);
            FMA2(aba, e2, gb.y, aba); FMA2(asa, e2, gs.y, asa);
            ADD2(d2, xpb[1], nm.y); MUL2(e2, d2, d2);
            FMA2(abb, e2, gb.y, abb); FMA2(asb, e2, gs.y, asb);
        }
        {   // pairs 2,3
            ulonglong2 nm = *(const ulonglong2*)&sh_nm[j][2];
            ulonglong2 gb = *(const ulonglong2*)&sh_gb[j][2];
            ulonglong2 gs = *(const ulonglong2*)&sh_gs[j][2];
            ADD2(d2, xpa[2], nm.x); MUL2(e2, d2, d2);
            FMA2(aba, e2, gb.x, aba); FMA2(asa, e2, gs.x, asa);
            ADD2(d2, xpb[2], nm.x); MUL2(e2, d2, d2);
            FMA2(abb, e2, gb.x, abb); FMA2(asb, e2, gs.x, asb);
            ADD2(d2, xpa[3], nm.y); MUL2(e2, d2, d2);
            FMA2(aba, e2, gb.y, aba); FMA2(asa, e2, gs.y, asa);
            ADD2(d2, xpb[3], nm.y); MUL2(e2, d2, d2);
            FMA2(abb, e2, gb.y, abb); FMA2(asb, e2, gs.y, asb);
        }

        float l0, l1, q0, q1;
        UNPACK2(l0, l1, aba); UNPACK2(q0, q1, asa);
        float Ua = ex2f(l0 + l1);
        float La = ex2f(q0 + q1);
        UNPACK2(l0, l1, abb); UNPACK2(q0, q1, asb);
        float Ub = ex2f(l0 + l1);
        float Lb = ex2f(q0 + q1);

        float4 sc = shScan[j];
        s0a  = fmaf(sc.x, La, s0a);   t0a  += La;
        s0ra = fmaf(sc.w, Ua, s0ra);  t0ra += Ua;
        s0b  = fmaf(sc.x, Lb, s0b);   t0b  += Lb;
        s0rb = fmaf(sc.w, Ub, s0rb);  t0rb += Ub;
        shD[j][t] = Ua - La;
        shD[j][t + THREADS] = Ub - Lb;
    }

    float lefta  = __fdividef(s0a,  t0a);
    float righta = __fdividef(s0ra, t0ra);
    float leftb  = __fdividef(s0b,  t0b);
    float rightb = __fdividef(s0rb, t0rb);

    float csa = 0.f, cta = 0.f, csra = 0.f, ctra = 0.f;
    float csb = 0.f, ctb = 0.f, csrb = 0.f, ctrb = 0.f;
    const float* shDf = &shD[0][0];
    #pragma unroll
    for (int j = 0; j < R; j++) {
        float4 sc = shScan[j];
        // Left scan: storage is already c1-sorted -> compile-time offsets.
        float dja = shD[j][t];
        float djb = shD[j][t + THREADS];
        csa = fmaf(sc.x, dja, csa);  cta += dja;
        csb = fmaf(sc.x, djb, csb);  ctb += djb;
        lefta = fminf(lefta, __fdividef(s0a + csa, t0a + cta));
        leftb = fminf(leftb, __fdividef(s0b + csb, t0b + ctb));
        // Right scan: c2-sorted order via runtime slot offset (same-thread column).
        int off = __float_as_int(sc.z);
        float dqa = shDf[off + t];
        float dqb = shDf[off + t + THREADS];
        csra = fmaf(sc.y, dqa, csra);  ctra += dqa;
        csrb = fmaf(sc.y, dqb, csrb);  ctrb += dqb;
        // dr = L - U = -dq  =>  ratio = (s0r - csr)/(t0r - ctr)
        righta = fmaxf(righta, __fdividef(s0ra - csra, t0ra - ctra));
        rightb = fmaxf(rightb, __fdividef(s0rb - csrb, t0rb - ctrb));
    }

    if (ia < n) out[ia] = 0.5f * (lefta + righta);
    if (ib < n) out[ib] = 0.5f * (leftb + rightb);
}

extern "C" void kernel_launch(void* const* d_in, const int* in_sizes, int n_in,
                              void* d_out, int out_size) {
    const float* x  = (const float*)d_in[0];
    const float* W  = (const float*)d_in[1];
    const float* c1 = (const float*)d_in[2];
    const float* c2 = (const float*)d_in[3];
    float* out = (float*)d_out;
    int n = out_size;  // one output per row

    int blocks = (n + ROWS_PER_CTA - 1) / ROWS_PER_CTA;
    t2fls_kernel<<<blocks, THREADS>>>(x, W, c1, c2, out, n);
}

// round 8
// speedup vs baseline: 1.3088x; 1.0718x over previous
#include <cuda_runtime.h>

#define R 16
#define A 8
#define THREADS 256

__device__ __forceinline__ float ex2f(float x) {
    float r;
    asm("ex2.approx.f32 %0, %1;" : "=f"(r) : "f"(x));
    return r;
}

__global__ __launch_bounds__(THREADS)   // no min-blocks: let ptxas pick regs, NO spills
void t2fls_kernel(const float* __restrict__ x_in,
                  const float* __restrict__ W,
                  const float* __restrict__ c1,
                  const float* __restrict__ c2,
                  float* __restrict__ out, int n)
{
    // d = U-L per (rule, row). Column t is touched only by thread t.
    __shared__ float shD[R][THREADS];                       // 16 KB
    // Coefficients in c1-sorted rule order, natural feature order (float4-loadable).
    __shared__ __align__(16) float sh_nm[R][A];             // negated centers
    __shared__ __align__(16) float sh_gb[R][A];             // -0.5*log2(e)/smax^2 (U)
    __shared__ __align__(16) float sh_gs[R][A];             // -0.5*log2(e)/smin^2 (L)
    // Per sorted slot j: (c1s[j], c2s[j], as_float(q[j]*THREADS), c2[p1[j]])
    __shared__ float4 shScan[R];
    __shared__ int   sh_p1[R], sh_inv1[R], sh_p2[R];
    __shared__ float sh_c1s[R], sh_c2s[R];

    int t = threadIdx.x;

    // ---- Phase A: parallel rank-sort of c1 (threads 0..15) and c2 (threads 16..31) ----
    if (t < R) {
        float cj = c1[t];
        int rank = 0;
        #pragma unroll
        for (int i = 0; i < R; i++) {
            float ci = c1[i];
            rank += (ci < cj) || (ci == cj && i < t);   // stable
        }
        sh_p1[rank] = t;
        sh_inv1[t] = rank;
        sh_c1s[rank] = cj;
    } else if (t < 2 * R) {
        int j = t - R;
        float cj = c2[j];
        int rank = 0;
        #pragma unroll
        for (int i = 0; i < R; i++) {
            float ci = c2[i];
            rank += (ci < cj) || (ci == cj && i < j);   // stable
        }
        sh_p2[rank] = j;
        sh_c2s[rank] = cj;
    }
    __syncthreads();

    // ---- Phase B: coefficient transform into c1-sorted layout ----
    if (t < R * A) {
        int r = t >> 3, a = t & 7;
        // offsets = A*r + a == t ; m = W[t], s1 = W[t+1], s2 = W[t+2]
        float m  = W[t];
        float s1 = W[t + 1];
        float s2 = W[t + 2];
        float smax = fmaxf(s1, s2);
        float smin = fminf(s1, s2);
        const float k = -0.5f * 1.44269504088896340736f;  // -0.5 * log2(e)
        int slot = sh_inv1[r];
        sh_nm[slot][a] = -m;
        sh_gb[slot][a] = k / (smax * smax);
        sh_gs[slot][a] = k / (smin * smin);
    }
    if (t < R) {
        int q = sh_inv1[sh_p2[t]];   // slot (in c1-order storage) of rule p2[t]
        shScan[t] = make_float4(sh_c1s[t], sh_c2s[t],
                                __int_as_float(q * THREADS),
                                c2[sh_p1[t]]);           // c2 value of rule at c1-slot t
    }
    __syncthreads();

    int i = blockIdx.x * THREADS + t;
    if (i >= n) return;

    // Load the 8-feature row with two float4s.
    const float4* xp = (const float4*)(x_in + (size_t)i * A);
    float4 xa = xp[0];
    float4 xb = xp[1];

    float s0 = 0.f, t0 = 0.f;     // sum(c1*L), sum(L)
    float s0r = 0.f, t0r = 0.f;   // sum(c2*U), sum(U)

    #pragma unroll 4
    for (int j = 0; j < R; j++) {
        float4 nm0 = *(const float4*)&sh_nm[j][0];
        float4 nm1 = *(const float4*)&sh_nm[j][4];
        float4 gb0 = *(const float4*)&sh_gb[j][0];
        float4 gb1 = *(const float4*)&sh_gb[j][4];
        float4 gs0 = *(const float4*)&sh_gs[j][0];
        float4 gs1 = *(const float4*)&sh_gs[j][4];

        float su = 0.f, sl = 0.f, d, e;
        d = xa.x + nm0.x; e = d * d; su = fmaf(e, gb0.x, su); sl = fmaf(e, gs0.x, sl);
        d = xa.y + nm0.y; e = d * d; su = fmaf(e, gb0.y, su); sl = fmaf(e, gs0.y, sl);
        d = xa.z + nm0.z; e = d * d; su = fmaf(e, gb0.z, su); sl = fmaf(e, gs0.z, sl);
        d = xa.w + nm0.w; e = d * d; su = fmaf(e, gb0.w, su); sl = fmaf(e, gs0.w, sl);
        d = xb.x + nm1.x; e = d * d; su = fmaf(e, gb1.x, su); sl = fmaf(e, gs1.x, sl);
        d = xb.y + nm1.y; e = d * d; su = fmaf(e, gb1.y, su); sl = fmaf(e, gs1.y, sl);
        d = xb.z + nm1.z; e = d * d; su = fmaf(e, gb1.z, su); sl = fmaf(e, gs1.z, sl);
        d = xb.w + nm1.w; e = d * d; su = fmaf(e, gb1.w, su); sl = fmaf(e, gs1.w, sl);

        float U = ex2f(su);   // prod_a mu_big  = exp2(sum of scaled exponents)
        float L = ex2f(sl);   // prod_a mu_small

        float4 sc = shScan[j];
        s0  = fmaf(sc.x, L, s0);   t0  += L;    // sc.x = c1 of this (sorted) rule
        s0r = fmaf(sc.w, U, s0r);  t0r += U;    // sc.w = c2 of this rule
        shD[j][t] = U - L;
    }

    float left  = __fdividef(s0,  t0);
    float right = __fdividef(s0r, t0r);

    float cs = 0.f, ct = 0.f, csr = 0.f, ctr = 0.f;
    const float* shDf = &shD[0][0];
    #pragma unroll
    for (int j = 0; j < R; j++) {
        float4 sc = shScan[j];
        // Left scan: storage is already c1-sorted -> compile-time offsets.
        float dj = shD[j][t];
        cs = fmaf(sc.x, dj, cs);
        ct += dj;
        left = fminf(left, __fdividef(s0 + cs, t0 + ct));
        // Right scan: c2-sorted order via runtime slot offset (same-thread column).
        int off = __float_as_int(sc.z);
        float dq = shDf[off + t];           // = U - L of rule p2[j]
        csr = fmaf(sc.y, dq, csr);          // accumulates sum c2s*(U-L)
        ctr += dq;
        // dr = L - U = -dq  =>  ratio = (s0r - csr)/(t0r - ctr)
        right = fmaxf(right, __fdividef(s0r - csr, t0r - ctr));
    }

    out[i] = 0.5f * (left + right);
}

extern "C" void kernel_launch(void* const* d_in, const int* in_sizes, int n_in,
                              void* d_out, int out_size) {
    const float* x  = (const float*)d_in[0];
    const float* W  = (const float*)d_in[1];
    const float* c1 = (const float*)d_in[2];
    const float* c2 = (const float*)d_in[3];
    float* out = (float*)d_out;
    int n = out_size;  // one output per row

    int blocks = (n + THREADS - 1) / THREADS;
    t2fls_kernel<<<blocks, THREADS>>>(x, W, c1, c2, out, n);
}